// round 14
// baseline (speedup 1.0000x reference)
#include <cuda_runtime.h>
#include <math.h>

#define Bn  16
#define Dn  192
#define TXn 512
#define TYn 2048
#define NEGV (-1e9f)

// ---- scratch (device globals; no allocation allowed) ----
__device__ __align__(16) float g_nc  [Bn * TYn * TXn];  // 64 MB neg_cent
__device__ __align__(16) float g_bms [Bn * Dn * TXn];
__device__ __align__(16) float g_bs  [Bn * Dn * TXn];
__device__ __align__(16) float g_cvec[Bn * TXn];
__device__ __align__(16) float g_cpart[8 * Bn * TXn];
__device__ int   g_path[Bn * TYn];

// packed fp32x2 FMA (Blackwell)
__device__ __forceinline__ void fma2(unsigned long long& d,
                                     unsigned long long a,
                                     unsigned long long b) {
    asm("fma.rn.f32x2 %0, %1, %2, %0;" : "+l"(d) : "l"(a), "l"(b));
}
#define PACKDUP(dst, f)                                                      \
    asm("mov.b64 %0, {%1, %1};" : "=l"(dst) : "r"(__float_as_uint(f)))

__device__ __forceinline__ void cp16(float* dst_smem, const float* src) {
    unsigned int d = (unsigned int)__cvta_generic_to_shared(dst_smem);
    asm volatile("cp.async.cg.shared.global [%0], [%1], 16;" :: "r"(d), "l"(src));
}
#define CP_COMMIT() asm volatile("cp.async.commit_group;")
#define CP_WAIT2()  asm volatile("cp.async.wait_group 2;" ::: "memory")
#define CP_WAIT1()  asm volatile("cp.async.wait_group 1;" ::: "memory")
#define CP_WAIT0()  asm volatile("cp.async.wait_group 0;" ::: "memory")

// ---------------------------------------------------------------------------
// Kernel 1: prep — 8 D-chunks in parallel, deterministic partials
// ---------------------------------------------------------------------------
__global__ void prep_kernel(const float* __restrict__ xm,
                            const float* __restrict__ xl) {
    int b  = blockIdx.y;
    int dc = blockIdx.z;
    int x  = blockIdx.x * 128 + threadIdx.x;
    const float* xmb = xm + b * Dn * TXn;
    const float* xlb = xl + b * Dn * TXn;
    float* bms = g_bms + b * Dn * TXn;
    float* bs  = g_bs  + b * Dn * TXn;
    float c = 0.0f;
    int d0 = dc * 24;
    #pragma unroll 4
    for (int d = d0; d < d0 + 24; d++) {
        float m = xmb[d * TXn + x];
        float l = xlb[d * TXn + x];
        float s = expf(-2.0f * l);
        bs [d * TXn + x] = s;
        bms[d * TXn + x] = m * s;
        c += (-l) + (-0.5f * m * m * s);
    }
    g_cpart[dc * (Bn * TXn) + b * TXn + x] = c;
}

__global__ void combine_kernel() {
    int i = blockIdx.x * 256 + threadIdx.x;
    float c = -(float)Dn * 0.91893853320467274f;
    #pragma unroll
    for (int p = 0; p < 8; p++) c += g_cpart[p * (Bn * TXn) + i];
    g_cvec[i] = c;
}

// ---------------------------------------------------------------------------
// Kernel 2: nc GEMM — exact R10 version (best measured: 201.5us)
// ---------------------------------------------------------------------------
__global__ __launch_bounds__(256) void nc_gemm_kernel(const float* __restrict__ z) {
    int bx = blockIdx.x;
    int by = blockIdx.y;
    int b  = blockIdx.z;
    if (bx > by) return;
    if (bx <= by - 13) return;

    __shared__ float s_z [8][128];
    __shared__ float s_z2[8][128];
    __shared__ float s_ms[8][128];
    __shared__ float s_s [8][128];

    int tid = threadIdx.x;
    int lr = tid >> 5;
    int lc = (tid & 31) * 4;
    int ty = tid >> 4;
    int tx = tid & 15;
    int bsplit = ((lc >> 2) & 1) * 64 + (lc >> 3) * 4;

    const float* zb  = z     + b * Dn * TYn + by * 128;
    const float* msb = g_bms + b * Dn * TXn + bx * 128;
    const float* ssb = g_bs  + b * Dn * TXn + bx * 128;

    unsigned long long acc[8][4];
    #pragma unroll
    for (int i = 0; i < 8; i++)
        #pragma unroll
        for (int j = 0; j < 4; j++) acc[i][j] = 0ull;

    float4 az  = *(const float4*)(zb  + lr * TYn + lc);
    float4 ams = *(const float4*)(msb + lr * TXn + lc);
    float4 ass = *(const float4*)(ssb + lr * TXn + lc);

    for (int c = 0; c < Dn / 8; c++) {
        __syncthreads();
        {
            *(float4*)&s_z[lr][lc] = az;
            float4 az2 = make_float4(-0.5f * az.x * az.x, -0.5f * az.y * az.y,
                                     -0.5f * az.z * az.z, -0.5f * az.w * az.w);
            *(float4*)&s_z2[lr][lc] = az2;
            *(float4*)&s_ms[lr][bsplit] = ams;
            *(float4*)&s_s [lr][bsplit] = ass;
        }
        __syncthreads();

        if (c + 1 < Dn / 8) {
            int d0 = (c + 1) * 8;
            az  = *(const float4*)(zb  + (d0 + lr) * TYn + lc);
            ams = *(const float4*)(msb + (d0 + lr) * TXn + lc);
            ass = *(const float4*)(ssb + (d0 + lr) * TXn + lc);
        }

        #pragma unroll
        for (int kk = 0; kk < 8; kk++) {
            unsigned long long a1[8], a2[8], b1[4], b2[4];
            {
                float4 t0 = *(const float4*)&s_z[kk][ty * 8];
                float4 t1 = *(const float4*)&s_z[kk][ty * 8 + 4];
                PACKDUP(a1[0], t0.x); PACKDUP(a1[1], t0.y);
                PACKDUP(a1[2], t0.z); PACKDUP(a1[3], t0.w);
                PACKDUP(a1[4], t1.x); PACKDUP(a1[5], t1.y);
                PACKDUP(a1[6], t1.z); PACKDUP(a1[7], t1.w);
            }
            {
                float4 t0 = *(const float4*)&s_z2[kk][ty * 8];
                float4 t1 = *(const float4*)&s_z2[kk][ty * 8 + 4];
                PACKDUP(a2[0], t0.x); PACKDUP(a2[1], t0.y);
                PACKDUP(a2[2], t0.z); PACKDUP(a2[3], t0.w);
                PACKDUP(a2[4], t1.x); PACKDUP(a2[5], t1.y);
                PACKDUP(a2[6], t1.z); PACKDUP(a2[7], t1.w);
            }
            {
                ulonglong2 lo = *(const ulonglong2*)&s_ms[kk][tx * 4];
                ulonglong2 hi = *(const ulonglong2*)&s_ms[kk][64 + tx * 4];
                b1[0]=lo.x; b1[1]=lo.y; b1[2]=hi.x; b1[3]=hi.y;
            }
            {
                ulonglong2 lo = *(const ulonglong2*)&s_s[kk][tx * 4];
                ulonglong2 hi = *(const ulonglong2*)&s_s[kk][64 + tx * 4];
                b2[0]=lo.x; b2[1]=lo.y; b2[2]=hi.x; b2[3]=hi.y;
            }
            #pragma unroll
            for (int i = 0; i < 8; i++)
                #pragma unroll
                for (int j = 0; j < 4; j++) {
                    fma2(acc[i][j], a1[i], b1[j]);
                    fma2(acc[i][j], a2[i], b2[j]);
                }
        }
    }

    float cv[8];
    *(float4*)&cv[0] = *(const float4*)(g_cvec + b * TXn + bx * 128 + tx * 8);
    *(float4*)&cv[4] = *(const float4*)(g_cvec + b * TXn + bx * 128 + tx * 8 + 4);

    float* outp = g_nc + (size_t)b * TYn * TXn + (size_t)(by * 128 + ty * 8) * TXn
                + bx * 128 + tx * 8;
    #pragma unroll
    for (int i = 0; i < 8; i++) {
        float2 f0 = *(float2*)&acc[i][0];
        float2 f1 = *(float2*)&acc[i][1];
        float2 f2 = *(float2*)&acc[i][2];
        float2 f3 = *(float2*)&acc[i][3];
        float4 o0 = make_float4(f0.x + cv[0], f0.y + cv[1], f1.x + cv[2], f1.y + cv[3]);
        float4 o1 = make_float4(f2.x + cv[4], f2.y + cv[5], f3.x + cv[6], f3.y + cv[7]);
        *(float4*)(outp + (size_t)i * TXn)     = o0;
        *(float4*)(outp + (size_t)i * TXn + 4) = o1;
    }
}

// ---------------------------------------------------------------------------
// Kernel 3: MAS — 16 warps/batch (4/SMSP), 2 cols/lane (32 own + 32 halo per
// warp), exact halo exchange every 16 rows. Direction-bit words keep the R13
// 4-col x 8-row layout via a lane-pair shfl merge, so backtrack is unchanged.
// Block-shared 4-buffer cp.async feed (2 cp16/thread per chunk).
// ---------------------------------------------------------------------------
#define ROWP2(Y, NEXTADDR, MASKED)                                           \
  {                                                                          \
    unsigned int bb = (lv > v[0] ? 1u : 0u) | (v[0] > v[1] ? 2u : 0u);       \
    bits_acc |= bb << ((((Y) & 7) * 4) + sh2);                               \
    float2 cur = pf;                                                         \
    pf = *(const float2*)(NEXTADDR);                                         \
    float nv1 = cur.y + fmaxf(v[1], v[0]);                                   \
    float nv0 = cur.x + fmaxf(v[0], lv);                                     \
    if (MASKED) {                                                            \
      int ylim = (Y) - c0;                                                   \
      if (0 > ylim) nv0 = NEGV;                                              \
      if (1 > ylim) nv1 = NEGV;                                              \
    }                                                                        \
    v[0] = nv0; v[1] = nv1;                                                  \
    lv = __shfl_up_sync(0xffffffffu, v[1], 1);                               \
    if (lane == 0) lv = NEGV;                                                \
    if (((Y) & 7) == 7) {                                                    \
      unsigned int mg = bits_acc | __shfl_down_sync(0xffffffffu, bits_acc, 1);\
      if (lane >= 16 && ((lane & 1) == 0))                                   \
        s_dirs32[((Y) >> 3) * 128 + (c0 >> 2)] = mg;                         \
      bits_acc = 0u;                                                         \
    }                                                                        \
  }

#define MAS_EXCH16()                                                         \
  {                                                                          \
    if (lane >= 16)                                                          \
      *(float2*)&s_exch[w * 32 + (lane - 16) * 2]                            \
          = make_float2(v[0], v[1]);                                         \
    __syncthreads();                                                         \
    if (w > 0 && lane < 16) {                                                \
      float2 e = *(const float2*)&s_exch[(w - 1) * 32 + lane * 2];           \
      v[0] = e.x; v[1] = e.y;                                                \
    }                                                                        \
    __syncthreads();                                                         \
    lv = __shfl_up_sync(0xffffffffu, v[1], 1);                               \
    if (lane == 0) lv = NEGV;                                                \
  }

// block-shared chunk load: 8 rows x 512 cols = 16KB; 512 threads x 2 cp16
#define LOADC_S(C, B)                                                        \
  {                                                                          \
    const float* s2 = nc + (size_t)(C) * 8 * TXn;                            \
    float* d2 = tiles + (B) * 4096;                                          \
    cp16(d2 + tid * 4, s2 + tid * 4);                                        \
    cp16(d2 + (tid + 512) * 4, s2 + (tid + 512) * 4);                        \
    CP_COMMIT();                                                             \
  }

__global__ __launch_bounds__(512) void mas_kernel(const float* __restrict__ logw,
                                                  float* __restrict__ out_llen,
                                                  float* __restrict__ out_attn) {
    extern __shared__ unsigned char s_dyn[];
    unsigned int* s_dirs32 = (unsigned int*)s_dyn;       // 128 KB
    float* tiles = (float*)(s_dyn + TYn * 64);           // 4 * 16KB = 64 KB
    __shared__ float s_exch[16 * 32];
    __shared__ unsigned short path_sm[TYn];
    __shared__ int w_sm[TXn];
    __shared__ float s_red[16];

    int b = blockIdx.x;
    int tid = threadIdx.x;
    int w = tid >> 5, lane = tid & 31;
    const float* nc = g_nc + (size_t)b * TYn * TXn;
    int c0 = w * 32 - 32 + lane * 2;             // negative in warp-0 halo
    int ldoff = (c0 < 0) ? (lane * 2) : c0;      // clamped (junk stays ~NEG)
    int sh2 = (lane & 1) * 2;

    float v[2];
    v[0] = NEGV; v[1] = NEGV;
    if (c0 == 0) v[0] = nc[0];
    unsigned int bits_acc = 0u;

    const int NCH = TYn / 8;                     // 256

    LOADC_S(0, 0);
    LOADC_S(1, 1);
    LOADC_S(2, 2);
    CP_WAIT2();
    __syncthreads();                             // chunk 0 fully visible

    float lv = __shfl_up_sync(0xffffffffu, v[1], 1);
    if (lane == 0) lv = NEGV;
    float2 pf = *(const float2*)(tiles + 512 + ldoff);   // buf0 row 1

    // chunk 0: rows 1..7
    {
        float* bp = tiles;
        ROWP2(1, bp + 2 * 512 + ldoff, 1);
        ROWP2(2, bp + 3 * 512 + ldoff, 1);
        ROWP2(3, bp + 4 * 512 + ldoff, 1);
        ROWP2(4, bp + 5 * 512 + ldoff, 1);
        ROWP2(5, bp + 6 * 512 + ldoff, 1);
        ROWP2(6, bp + 7 * 512 + ldoff, 1);
        LOADC_S(3, 3);
        CP_WAIT2();
        __syncthreads();                         // chunk 1 fully visible
        ROWP2(7, tiles + 1 * 4096 + ldoff, 1);   // pf <- buf1 row 0
    }

    for (int c = 1; c < NCH; c++) {
        float* bp = tiles + (c & 3) * 4096;
        int yb = c * 8;
        int M = (c < 64);
        if (M) {
            ROWP2(yb + 0, bp + 1 * 512 + ldoff, 1);
            ROWP2(yb + 1, bp + 2 * 512 + ldoff, 1);
            ROWP2(yb + 2, bp + 3 * 512 + ldoff, 1);
            ROWP2(yb + 3, bp + 4 * 512 + ldoff, 1);
            ROWP2(yb + 4, bp + 5 * 512 + ldoff, 1);
            ROWP2(yb + 5, bp + 6 * 512 + ldoff, 1);
            ROWP2(yb + 6, bp + 7 * 512 + ldoff, 1);
        } else {
            ROWP2(yb + 0, bp + 1 * 512 + ldoff, 0);
            ROWP2(yb + 1, bp + 2 * 512 + ldoff, 0);
            ROWP2(yb + 2, bp + 3 * 512 + ldoff, 0);
            ROWP2(yb + 3, bp + 4 * 512 + ldoff, 0);
            ROWP2(yb + 4, bp + 5 * 512 + ldoff, 0);
            ROWP2(yb + 5, bp + 6 * 512 + ldoff, 0);
            ROWP2(yb + 6, bp + 7 * 512 + ldoff, 0);
        }
        if (c + 3 < NCH) LOADC_S(c + 3, (c + 3) & 3);
        if (c <= NCH - 4) { CP_WAIT2(); }
        else if (c == NCH - 3) { CP_WAIT1(); }
        else { CP_WAIT0(); }
        __syncthreads();
        float* np = (c + 1 < NCH) ? (tiles + ((c + 1) & 3) * 4096 + ldoff)
                                  : (bp + 7 * 512 + ldoff);
        if (M) { ROWP2(yb + 7, np, 1); } else { ROWP2(yb + 7, np, 0); }
        if ((c & 1) == 1 && c + 1 < NCH) MAS_EXCH16();   // every 16 rows
    }
    __syncthreads();

    // pipelined backtrack: 8-row blocks, 3 candidate words per block
    if (tid == 0) {
        int idx = TXn - 1;
        for (int k = (TYn / 8) - 1; k >= 0; k--) {
            int g = idx >> 2;
            unsigned int w0 = s_dirs32[k * 128 + g];
            unsigned int w1 = (g >= 1) ? s_dirs32[k * 128 + g - 1] : 0u;
            unsigned int w2 = (g >= 2) ? s_dirs32[k * 128 + g - 2] : 0u;
            #pragma unroll
            for (int r = 7; r >= 0; r--) {
                int yy = k * 8 + r;
                if (yy == 0) break;
                path_sm[yy] = (unsigned short)idx;
                int gg = idx >> 2;
                unsigned int word = (gg == g) ? w0 : ((gg == g - 1) ? w1 : w2);
                int bitpos = ((yy & 7) << 2) + (idx & 3);
                idx -= (int)((word >> bitpos) & 1u);
            }
        }
        path_sm[0] = (unsigned short)idx;
    }
    __syncthreads();

    for (int x = tid; x < TXn; x += 512) w_sm[x] = 0;
    __syncthreads();

    for (int yy = tid; yy < TYn; yy += 512) {
        int px = path_sm[yy];
        g_path[b * TYn + yy] = px;
        atomicAdd(&w_sm[px], 1);
        out_attn[(size_t)b * TYn * TXn + (size_t)yy * TXn + px] = 1.0f;
    }
    __syncthreads();

    float part = 0.0f;
    if (tid < TXn) {
        float lw = logw[b * TXn + tid];
        float d  = lw - logf((float)w_sm[tid] + 1e-6f);
        part = d * d;
    }
    #pragma unroll
    for (int o = 16; o > 0; o >>= 1)
        part += __shfl_down_sync(0xffffffffu, part, o);
    if (lane == 0) s_red[w] = part;
    __syncthreads();
    if (tid == 0) {
        float s = 0.0f;
        #pragma unroll
        for (int i = 0; i < 16; i++) s += s_red[i];
        out_llen[b] = s;
    }
}

// ---------------------------------------------------------------------------
// Kernel 4: gather
// ---------------------------------------------------------------------------
__global__ void gather_kernel(const float* __restrict__ xm,
                              const float* __restrict__ xl,
                              float* __restrict__ out_main) {
    int b  = blockIdx.y;
    int dc = blockIdx.z;
    int y  = blockIdx.x * 256 + threadIdx.x;
    int px = g_path[b * TYn + y];
    const float* xmb = xm + b * Dn * TXn + px;
    const float* xlb = xl + b * Dn * TXn + px;
    float* o = out_main + (size_t)b * 2 * Dn * TYn + y;
    int d0 = dc * 24;
    #pragma unroll 4
    for (int d = d0; d < d0 + 24; d++)
        o[(size_t)d * TYn] = xmb[(size_t)d * TXn];
    #pragma unroll 4
    for (int d = d0; d < d0 + 24; d++)
        o[(size_t)(Dn + d) * TYn] = xlb[(size_t)d * TXn];
}

// ---------------------------------------------------------------------------
extern "C" void kernel_launch(void* const* d_in, const int* in_sizes, int n_in,
                              void* d_out, int out_size) {
    const float* xm   = (const float*)d_in[0];
    const float* xl   = (const float*)d_in[1];
    const float* z    = (const float*)d_in[2];
    const float* logw = (const float*)d_in[3];

    float* out       = (float*)d_out;
    const size_t OM  = (size_t)Bn * 2 * Dn * TYn;
    float* out_main  = out;
    float* out_llen  = out + OM;
    float* out_attn  = out + OM + Bn;

    int mas_smem = TYn * 64 + 4 * 4096 * (int)sizeof(float);   // 128K + 64K
    cudaFuncSetAttribute(mas_kernel,
                         cudaFuncAttributeMaxDynamicSharedMemorySize, mas_smem);

    // kernel order: prep(1) combine(2) gemm(3) mas(4 - captured) gather(5)
    prep_kernel<<<dim3(TXn / 128, Bn, 8), 128>>>(xm, xl);
    combine_kernel<<<(Bn * TXn) / 256, 256>>>();
    nc_gemm_kernel<<<dim3(TXn / 128, TYn / 128, Bn), 256>>>(z);
    cudaMemsetAsync(out_attn, 0, (size_t)Bn * TYn * TXn * sizeof(float));
    mas_kernel<<<Bn, 512, mas_smem>>>(logw, out_llen, out_attn);
    gather_kernel<<<dim3(TYn / 256, Bn, 8), 256>>>(xm, xl, out_main);
}

// round 15
// speedup vs baseline: 1.6464x; 1.6464x over previous
#include <cuda_runtime.h>
#include <math.h>

#define Bn  16
#define Dn  192
#define TXn 512
#define TYn 2048
#define NEGV (-1e9f)

// ---- scratch (device globals; no allocation allowed) ----
__device__ __align__(16) float g_nc  [Bn * TYn * TXn];  // 64 MB neg_cent
__device__ __align__(16) float g_bms [Bn * Dn * TXn];
__device__ __align__(16) float g_bs  [Bn * Dn * TXn];
__device__ __align__(16) float g_cvec[Bn * TXn];
__device__ __align__(16) float g_cpart[8 * Bn * TXn];
__device__ int   g_path[Bn * TYn];

// packed fp32x2 FMA (Blackwell)
__device__ __forceinline__ void fma2(unsigned long long& d,
                                     unsigned long long a,
                                     unsigned long long b) {
    asm("fma.rn.f32x2 %0, %1, %2, %0;" : "+l"(d) : "l"(a), "l"(b));
}
#define PACKDUP(dst, f)                                                      \
    asm("mov.b64 %0, {%1, %1};" : "=l"(dst) : "r"(__float_as_uint(f)))

__device__ __forceinline__ void cp16(float* dst_smem, const float* src) {
    unsigned int d = (unsigned int)__cvta_generic_to_shared(dst_smem);
    asm volatile("cp.async.cg.shared.global [%0], [%1], 16;" :: "r"(d), "l"(src));
}
#define CP_COMMIT() asm volatile("cp.async.commit_group;")
#define CP_WAIT3()  asm volatile("cp.async.wait_group 3;" ::: "memory")
#define CP_WAIT2()  asm volatile("cp.async.wait_group 2;" ::: "memory")
#define CP_WAIT1()  asm volatile("cp.async.wait_group 1;" ::: "memory")
#define CP_WAIT0()  asm volatile("cp.async.wait_group 0;" ::: "memory")

// ---------------------------------------------------------------------------
// Kernel 1: prep — 8 D-chunks in parallel, deterministic partials
// ---------------------------------------------------------------------------
__global__ void prep_kernel(const float* __restrict__ xm,
                            const float* __restrict__ xl) {
    int b  = blockIdx.y;
    int dc = blockIdx.z;
    int x  = blockIdx.x * 128 + threadIdx.x;
    const float* xmb = xm + b * Dn * TXn;
    const float* xlb = xl + b * Dn * TXn;
    float* bms = g_bms + b * Dn * TXn;
    float* bs  = g_bs  + b * Dn * TXn;
    float c = 0.0f;
    int d0 = dc * 24;
    #pragma unroll 4
    for (int d = d0; d < d0 + 24; d++) {
        float m = xmb[d * TXn + x];
        float l = xlb[d * TXn + x];
        float s = expf(-2.0f * l);
        bs [d * TXn + x] = s;
        bms[d * TXn + x] = m * s;
        c += (-l) + (-0.5f * m * m * s);
    }
    g_cpart[dc * (Bn * TXn) + b * TXn + x] = c;
}

__global__ void combine_kernel() {
    int i = blockIdx.x * 256 + threadIdx.x;
    float c = -(float)Dn * 0.91893853320467274f;
    #pragma unroll
    for (int p = 0; p < 8; p++) c += g_cpart[p * (Bn * TXn) + i];
    g_cvec[i] = c;
}

// ---------------------------------------------------------------------------
// Kernel 2: nc GEMM — exact R10 version (best measured: 201.5us)
// ---------------------------------------------------------------------------
__global__ __launch_bounds__(256) void nc_gemm_kernel(const float* __restrict__ z) {
    int bx = blockIdx.x;
    int by = blockIdx.y;
    int b  = blockIdx.z;
    if (bx > by) return;
    if (bx <= by - 13) return;

    __shared__ float s_z [8][128];
    __shared__ float s_z2[8][128];
    __shared__ float s_ms[8][128];
    __shared__ float s_s [8][128];

    int tid = threadIdx.x;
    int lr = tid >> 5;
    int lc = (tid & 31) * 4;
    int ty = tid >> 4;
    int tx = tid & 15;
    int bsplit = ((lc >> 2) & 1) * 64 + (lc >> 3) * 4;

    const float* zb  = z     + b * Dn * TYn + by * 128;
    const float* msb = g_bms + b * Dn * TXn + bx * 128;
    const float* ssb = g_bs  + b * Dn * TXn + bx * 128;

    unsigned long long acc[8][4];
    #pragma unroll
    for (int i = 0; i < 8; i++)
        #pragma unroll
        for (int j = 0; j < 4; j++) acc[i][j] = 0ull;

    float4 az  = *(const float4*)(zb  + lr * TYn + lc);
    float4 ams = *(const float4*)(msb + lr * TXn + lc);
    float4 ass = *(const float4*)(ssb + lr * TXn + lc);

    for (int c = 0; c < Dn / 8; c++) {
        __syncthreads();
        {
            *(float4*)&s_z[lr][lc] = az;
            float4 az2 = make_float4(-0.5f * az.x * az.x, -0.5f * az.y * az.y,
                                     -0.5f * az.z * az.z, -0.5f * az.w * az.w);
            *(float4*)&s_z2[lr][lc] = az2;
            *(float4*)&s_ms[lr][bsplit] = ams;
            *(float4*)&s_s [lr][bsplit] = ass;
        }
        __syncthreads();

        if (c + 1 < Dn / 8) {
            int d0 = (c + 1) * 8;
            az  = *(const float4*)(zb  + (d0 + lr) * TYn + lc);
            ams = *(const float4*)(msb + (d0 + lr) * TXn + lc);
            ass = *(const float4*)(ssb + (d0 + lr) * TXn + lc);
        }

        #pragma unroll
        for (int kk = 0; kk < 8; kk++) {
            unsigned long long a1[8], a2[8], b1[4], b2[4];
            {
                float4 t0 = *(const float4*)&s_z[kk][ty * 8];
                float4 t1 = *(const float4*)&s_z[kk][ty * 8 + 4];
                PACKDUP(a1[0], t0.x); PACKDUP(a1[1], t0.y);
                PACKDUP(a1[2], t0.z); PACKDUP(a1[3], t0.w);
                PACKDUP(a1[4], t1.x); PACKDUP(a1[5], t1.y);
                PACKDUP(a1[6], t1.z); PACKDUP(a1[7], t1.w);
            }
            {
                float4 t0 = *(const float4*)&s_z2[kk][ty * 8];
                float4 t1 = *(const float4*)&s_z2[kk][ty * 8 + 4];
                PACKDUP(a2[0], t0.x); PACKDUP(a2[1], t0.y);
                PACKDUP(a2[2], t0.z); PACKDUP(a2[3], t0.w);
                PACKDUP(a2[4], t1.x); PACKDUP(a2[5], t1.y);
                PACKDUP(a2[6], t1.z); PACKDUP(a2[7], t1.w);
            }
            {
                ulonglong2 lo = *(const ulonglong2*)&s_ms[kk][tx * 4];
                ulonglong2 hi = *(const ulonglong2*)&s_ms[kk][64 + tx * 4];
                b1[0]=lo.x; b1[1]=lo.y; b1[2]=hi.x; b1[3]=hi.y;
            }
            {
                ulonglong2 lo = *(const ulonglong2*)&s_s[kk][tx * 4];
                ulonglong2 hi = *(const ulonglong2*)&s_s[kk][64 + tx * 4];
                b2[0]=lo.x; b2[1]=lo.y; b2[2]=hi.x; b2[3]=hi.y;
            }
            #pragma unroll
            for (int i = 0; i < 8; i++)
                #pragma unroll
                for (int j = 0; j < 4; j++) {
                    fma2(acc[i][j], a1[i], b1[j]);
                    fma2(acc[i][j], a2[i], b2[j]);
                }
        }
    }

    float cv[8];
    *(float4*)&cv[0] = *(const float4*)(g_cvec + b * TXn + bx * 128 + tx * 8);
    *(float4*)&cv[4] = *(const float4*)(g_cvec + b * TXn + bx * 128 + tx * 8 + 4);

    float* outp = g_nc + (size_t)b * TYn * TXn + (size_t)(by * 128 + ty * 8) * TXn
                + bx * 128 + tx * 8;
    #pragma unroll
    for (int i = 0; i < 8; i++) {
        float2 f0 = *(float2*)&acc[i][0];
        float2 f1 = *(float2*)&acc[i][1];
        float2 f2 = *(float2*)&acc[i][2];
        float2 f3 = *(float2*)&acc[i][3];
        float4 o0 = make_float4(f0.x + cv[0], f0.y + cv[1], f1.x + cv[2], f1.y + cv[3]);
        float4 o1 = make_float4(f2.x + cv[4], f2.y + cv[5], f3.x + cv[6], f3.y + cv[7]);
        *(float4*)(outp + (size_t)i * TXn)     = o0;
        *(float4*)(outp + (size_t)i * TXn + 4) = o1;
    }
}

// ---------------------------------------------------------------------------
// Kernel 3: MAS — R13 structure (8 warps, 4 cols/lane, block-shared tiles)
// with a 5-BUFFER cp.async pipeline (wait_group 3 steady state) so the DRAM
// latency+transfer is spread over 4 chunk-times instead of 2.
// ---------------------------------------------------------------------------
#define ROWP(Y, NEXTADDR, MASKED)                                            \
  {                                                                          \
    unsigned int bb = (lv   > v[0] ? 1u : 0u) | (v[0] > v[1] ? 2u : 0u)      \
                    | (v[1] > v[2] ? 4u : 0u) | (v[2] > v[3] ? 8u : 0u);     \
    bits_acc |= bb << (((Y) & 7) * 4);                                       \
    float4 cur = pf;                                                         \
    pf = *(const float4*)(NEXTADDR);                                         \
    float nv3 = cur.w + fmaxf(v[3], v[2]);                                   \
    float nv2 = cur.z + fmaxf(v[2], v[1]);                                   \
    float nv1 = cur.y + fmaxf(v[1], v[0]);                                   \
    float nv0 = cur.x + fmaxf(v[0], lv);                                     \
    if (MASKED) {                                                            \
      int ylim = (Y) - c0;                                                   \
      if (0 > ylim) nv0 = NEGV;                                              \
      if (1 > ylim) nv1 = NEGV;                                              \
      if (2 > ylim) nv2 = NEGV;                                              \
      if (3 > ylim) nv3 = NEGV;                                              \
    }                                                                        \
    v[0] = nv0; v[1] = nv1; v[2] = nv2; v[3] = nv3;                          \
    lv = __shfl_up_sync(0xffffffffu, v[3], 1);                               \
    if (lane == 0) lv = NEGV;                                                \
    if (((Y) & 7) == 7) {                                                    \
      if (lane >= 16)                                                        \
        s_dirs32[((Y) >> 3) * 128 + w * 16 + (lane - 16)] = bits_acc;        \
      bits_acc = 0u;                                                         \
    }                                                                        \
  }

#define MAS_EXCH8P()                                                         \
  {                                                                          \
    if (lane >= 16)                                                          \
      *(float4*)&s_exch[w * 64 + (lane - 16) * 4]                            \
          = make_float4(v[0], v[1], v[2], v[3]);                             \
    __syncthreads();                                                         \
    if (w > 0 && lane < 16) {                                                \
      float4 e = *(const float4*)&s_exch[(w - 1) * 64 + lane * 4];           \
      v[0] = e.x; v[1] = e.y; v[2] = e.z; v[3] = e.w;                        \
    }                                                                        \
    __syncthreads();                                                         \
    lv = __shfl_up_sync(0xffffffffu, v[3], 1);                               \
    if (lane == 0) lv = NEGV;                                                \
  }

// block-shared chunk load: 8 rows x 512 cols = 16KB; each thread 4x cp16
#define LOADC_S(C, B)                                                        \
  {                                                                          \
    const float* s2 = nc + (size_t)(C) * 8 * TXn;                            \
    float* d2 = tiles + (B) * 4096;                                          \
    _Pragma("unroll") for (int i = 0; i < 4; i++)                            \
      cp16(d2 + (tid + i * 256) * 4, s2 + (tid + i * 256) * 4);              \
    CP_COMMIT();                                                             \
  }

__global__ __launch_bounds__(256) void mas_kernel(const float* __restrict__ logw,
                                                  float* __restrict__ out_llen,
                                                  float* __restrict__ out_attn) {
    extern __shared__ unsigned char s_dyn[];
    unsigned int* s_dirs32 = (unsigned int*)s_dyn;       // 128 KB
    float* tiles = (float*)(s_dyn + TYn * 64);           // 5 * 16KB = 80 KB
    __shared__ float s_exch[8 * 64];
    __shared__ unsigned short path_sm[TYn];
    __shared__ int w_sm[TXn];
    __shared__ float s_red[8];

    int b = blockIdx.x;
    int tid = threadIdx.x;
    int w = tid >> 5, lane = tid & 31;
    const float* nc = g_nc + (size_t)b * TYn * TXn;
    int c0 = (w - 1) * 64 + lane * 4;            // negative in warp-0 halo
    int ldoff = (c0 < 0) ? (lane * 4) : c0;

    float v[4];
    #pragma unroll
    for (int i = 0; i < 4; i++) v[i] = NEGV;
    if (c0 == 0) v[0] = nc[0];
    unsigned int bits_acc = 0u;

    const int NCH = TYn / 8;                     // 256

    LOADC_S(0, 0);
    LOADC_S(1, 1);
    LOADC_S(2, 2);
    LOADC_S(3, 3);
    CP_WAIT3();                                  // chunk 0 complete
    __syncthreads();

    float lv = __shfl_up_sync(0xffffffffu, v[3], 1);
    if (lane == 0) lv = NEGV;
    float4 pf = *(const float4*)(tiles + 512 + ldoff);   // buf0 row 1

    // chunk 0: rows 1..7
    {
        float* bp = tiles;                       // buf 0
        ROWP(1, bp + 2 * 512 + ldoff, 1);
        ROWP(2, bp + 3 * 512 + ldoff, 1);
        ROWP(3, bp + 4 * 512 + ldoff, 1);
        ROWP(4, bp + 5 * 512 + ldoff, 1);
        ROWP(5, bp + 6 * 512 + ldoff, 1);
        ROWP(6, bp + 7 * 512 + ldoff, 1);
        LOADC_S(4, 4);
        CP_WAIT3();                              // chunk 1 complete
        __syncthreads();
        ROWP(7, tiles + 1 * 4096 + ldoff, 1);    // pf <- buf1 row 0
    }

    int bufc = 1;
    for (int c = 1; c < NCH; c++) {
        float* bp = tiles + bufc * 4096;
        int yb = c * 8;
        int M = (c < 64);
        if (M) {
            ROWP(yb + 0, bp + 1 * 512 + ldoff, 1);
            ROWP(yb + 1, bp + 2 * 512 + ldoff, 1);
            ROWP(yb + 2, bp + 3 * 512 + ldoff, 1);
            ROWP(yb + 3, bp + 4 * 512 + ldoff, 1);
            ROWP(yb + 4, bp + 5 * 512 + ldoff, 1);
            ROWP(yb + 5, bp + 6 * 512 + ldoff, 1);
            ROWP(yb + 6, bp + 7 * 512 + ldoff, 1);
        } else {
            ROWP(yb + 0, bp + 1 * 512 + ldoff, 0);
            ROWP(yb + 1, bp + 2 * 512 + ldoff, 0);
            ROWP(yb + 2, bp + 3 * 512 + ldoff, 0);
            ROWP(yb + 3, bp + 4 * 512 + ldoff, 0);
            ROWP(yb + 4, bp + 5 * 512 + ldoff, 0);
            ROWP(yb + 5, bp + 6 * 512 + ldoff, 0);
            ROWP(yb + 6, bp + 7 * 512 + ldoff, 0);
        }
        // load chunk c+4 into buf (bufc-1)%5 (its chunk c-1 fully read in iter c-1)
        int lb = (bufc == 0) ? 4 : bufc - 1;
        if (c + 4 < NCH) LOADC_S(c + 4, lb);
        // ensure chunk c+1 complete: outstanding beyond it = min(3, NCH-c-2)
        int rem = NCH - c - 2;
        if (rem >= 3)      { CP_WAIT3(); }
        else if (rem == 2) { CP_WAIT2(); }
        else if (rem == 1) { CP_WAIT1(); }
        else               { CP_WAIT0(); }
        __syncthreads();
        int nb = (bufc == 4) ? 0 : bufc + 1;
        float* np = (c + 1 < NCH) ? (tiles + nb * 4096 + ldoff)
                                  : (bp + 7 * 512 + ldoff);
        if (M) { ROWP(yb + 7, np, 1); } else { ROWP(yb + 7, np, 0); }
        if ((c & 7) == 7 && c + 1 < NCH) MAS_EXCH8P();
        bufc = nb;
    }
    __syncthreads();

    // pipelined backtrack: 8-row blocks, 3 candidate words per block
    if (tid == 0) {
        int idx = TXn - 1;
        for (int k = (TYn / 8) - 1; k >= 0; k--) {
            int g = idx >> 2;
            unsigned int w0 = s_dirs32[k * 128 + g];
            unsigned int w1 = (g >= 1) ? s_dirs32[k * 128 + g - 1] : 0u;
            unsigned int w2 = (g >= 2) ? s_dirs32[k * 128 + g - 2] : 0u;
            #pragma unroll
            for (int r = 7; r >= 0; r--) {
                int yy = k * 8 + r;
                if (yy == 0) break;
                path_sm[yy] = (unsigned short)idx;
                int gg = idx >> 2;
                unsigned int word = (gg == g) ? w0 : ((gg == g - 1) ? w1 : w2);
                int bitpos = ((yy & 7) << 2) + (idx & 3);
                idx -= (int)((word >> bitpos) & 1u);
            }
        }
        path_sm[0] = (unsigned short)idx;
    }
    __syncthreads();

    for (int x = tid; x < TXn; x += 256) w_sm[x] = 0;
    __syncthreads();

    for (int yy = tid; yy < TYn; yy += 256) {
        int px = path_sm[yy];
        g_path[b * TYn + yy] = px;
        atomicAdd(&w_sm[px], 1);
        out_attn[(size_t)b * TYn * TXn + (size_t)yy * TXn + px] = 1.0f;
    }
    __syncthreads();

    float part = 0.0f;
    for (int x = tid; x < TXn; x += 256) {
        float lw = logw[b * TXn + x];
        float d  = lw - logf((float)w_sm[x] + 1e-6f);
        part += d * d;
    }
    #pragma unroll
    for (int o = 16; o > 0; o >>= 1)
        part += __shfl_down_sync(0xffffffffu, part, o);
    if (lane == 0) s_red[w] = part;
    __syncthreads();
    if (tid == 0) {
        float s = 0.0f;
        #pragma unroll
        for (int i = 0; i < 8; i++) s += s_red[i];
        out_llen[b] = s;
    }
}

// ---------------------------------------------------------------------------
// Kernel 4: gather
// ---------------------------------------------------------------------------
__global__ void gather_kernel(const float* __restrict__ xm,
                              const float* __restrict__ xl,
                              float* __restrict__ out_main) {
    int b  = blockIdx.y;
    int dc = blockIdx.z;
    int y  = blockIdx.x * 256 + threadIdx.x;
    int px = g_path[b * TYn + y];
    const float* xmb = xm + b * Dn * TXn + px;
    const float* xlb = xl + b * Dn * TXn + px;
    float* o = out_main + (size_t)b * 2 * Dn * TYn + y;
    int d0 = dc * 24;
    #pragma unroll 4
    for (int d = d0; d < d0 + 24; d++)
        o[(size_t)d * TYn] = xmb[(size_t)d * TXn];
    #pragma unroll 4
    for (int d = d0; d < d0 + 24; d++)
        o[(size_t)(Dn + d) * TYn] = xlb[(size_t)d * TXn];
}

// ---------------------------------------------------------------------------
extern "C" void kernel_launch(void* const* d_in, const int* in_sizes, int n_in,
                              void* d_out, int out_size) {
    const float* xm   = (const float*)d_in[0];
    const float* xl   = (const float*)d_in[1];
    const float* z    = (const float*)d_in[2];
    const float* logw = (const float*)d_in[3];

    float* out       = (float*)d_out;
    const size_t OM  = (size_t)Bn * 2 * Dn * TYn;
    float* out_main  = out;
    float* out_llen  = out + OM;
    float* out_attn  = out + OM + Bn;

    int mas_smem = TYn * 64 + 5 * 4096 * (int)sizeof(float);   // 128K + 80K
    cudaFuncSetAttribute(mas_kernel,
                         cudaFuncAttributeMaxDynamicSharedMemorySize, mas_smem);

    // kernel order: prep(1) combine(2) gemm(3) mas(4 - captured) gather(5)
    prep_kernel<<<dim3(TXn / 128, Bn, 8), 128>>>(xm, xl);
    combine_kernel<<<(Bn * TXn) / 256, 256>>>();
    nc_gemm_kernel<<<dim3(TXn / 128, TYn / 128, Bn), 256>>>(z);
    cudaMemsetAsync(out_attn, 0, (size_t)Bn * TYn * TXn * sizeof(float));
    mas_kernel<<<Bn, 256, mas_smem>>>(logw, out_llen, out_attn);
    gather_kernel<<<dim3(TYn / 256, Bn, 8), 256>>>(xm, xl, out_main);
}

// round 16
// speedup vs baseline: 1.9848x; 1.2056x over previous
#include <cuda_runtime.h>
#include <math.h>

#define Bn  16
#define Dn  192
#define TXn 512
#define TYn 2048
#define NEGV (-1e9f)

// ---- scratch (device globals; no allocation allowed) ----
__device__ __align__(16) float g_nc  [Bn * TYn * TXn];  // 64 MB neg_cent
__device__ __align__(16) float g_bms [Bn * Dn * TXn];
__device__ __align__(16) float g_bs  [Bn * Dn * TXn];
__device__ __align__(16) float g_cvec[Bn * TXn];
__device__ __align__(16) float g_cpart[8 * Bn * TXn];
__device__ int   g_path[Bn * TYn];
__device__ int   g_flags[Bn * 16];      // per (b, y-tile) completion counters
__device__ int   g_dummy_sink;

// packed fp32x2 FMA (Blackwell)
__device__ __forceinline__ void fma2(unsigned long long& d,
                                     unsigned long long a,
                                     unsigned long long b) {
    asm("fma.rn.f32x2 %0, %1, %2, %0;" : "+l"(d) : "l"(a), "l"(b));
}
#define PACKDUP(dst, f)                                                      \
    asm("mov.b64 %0, {%1, %1};" : "=l"(dst) : "r"(__float_as_uint(f)))

__device__ __forceinline__ void cp16(float* dst_smem, const float* src) {
    unsigned int d = (unsigned int)__cvta_generic_to_shared(dst_smem);
    asm volatile("cp.async.cg.shared.global [%0], [%1], 16;" :: "r"(d), "l"(src));
}
#define CP_COMMIT() asm volatile("cp.async.commit_group;")
#define CP_WAIT3()  asm volatile("cp.async.wait_group 3;" ::: "memory")
#define CP_WAIT2()  asm volatile("cp.async.wait_group 2;" ::: "memory")
#define CP_WAIT1()  asm volatile("cp.async.wait_group 1;" ::: "memory")
#define CP_WAIT0()  asm volatile("cp.async.wait_group 0;" ::: "memory")

__device__ __forceinline__ int tile_cnt(int T) {
    int lo = (T - 12 > 0) ? (T - 12) : 0;
    int hi = (T < 3) ? T : 3;
    return hi - lo + 1;
}

__global__ void dummy_kernel() { g_dummy_sink = 1; }

// ---------------------------------------------------------------------------
// Kernel 1: prep — 8 D-chunks in parallel, deterministic partials
// ---------------------------------------------------------------------------
__global__ void prep_kernel(const float* __restrict__ xm,
                            const float* __restrict__ xl) {
    int b  = blockIdx.y;
    int dc = blockIdx.z;
    int x  = blockIdx.x * 128 + threadIdx.x;
    const float* xmb = xm + b * Dn * TXn;
    const float* xlb = xl + b * Dn * TXn;
    float* bms = g_bms + b * Dn * TXn;
    float* bs  = g_bs  + b * Dn * TXn;
    float c = 0.0f;
    int d0 = dc * 24;
    #pragma unroll 4
    for (int d = d0; d < d0 + 24; d++) {
        float m = xmb[d * TXn + x];
        float l = xlb[d * TXn + x];
        float s = expf(-2.0f * l);
        bs [d * TXn + x] = s;
        bms[d * TXn + x] = m * s;
        c += (-l) + (-0.5f * m * m * s);
    }
    g_cpart[dc * (Bn * TXn) + b * TXn + x] = c;
}

__global__ void combine_kernel() {
    int i = blockIdx.x * 256 + threadIdx.x;
    float c = -(float)Dn * 0.91893853320467274f;
    #pragma unroll
    for (int p = 0; p < 8; p++) c += g_cpart[p * (Bn * TXn) + i];
    g_cvec[i] = c;
    if (blockIdx.x == 0 && threadIdx.x < Bn * 16)
        g_flags[threadIdx.x] = 0;                // reset producer flags per run
}

// ---------------------------------------------------------------------------
// MAS row / exchange / load macros (R15 proven versions; spin added at feed)
// ---------------------------------------------------------------------------
#define ROWP(Y, NEXTADDR, MASKED)                                            \
  {                                                                          \
    unsigned int bb = (lv   > v[0] ? 1u : 0u) | (v[0] > v[1] ? 2u : 0u)      \
                    | (v[1] > v[2] ? 4u : 0u) | (v[2] > v[3] ? 8u : 0u);     \
    bits_acc |= bb << (((Y) & 7) * 4);                                       \
    float4 cur = pf;                                                         \
    pf = *(const float4*)(NEXTADDR);                                         \
    float nv3 = cur.w + fmaxf(v[3], v[2]);                                   \
    float nv2 = cur.z + fmaxf(v[2], v[1]);                                   \
    float nv1 = cur.y + fmaxf(v[1], v[0]);                                   \
    float nv0 = cur.x + fmaxf(v[0], lv);                                     \
    if (MASKED) {                                                            \
      int ylim = (Y) - c0;                                                   \
      if (0 > ylim) nv0 = NEGV;                                              \
      if (1 > ylim) nv1 = NEGV;                                              \
      if (2 > ylim) nv2 = NEGV;                                              \
      if (3 > ylim) nv3 = NEGV;                                              \
    }                                                                        \
    v[0] = nv0; v[1] = nv1; v[2] = nv2; v[3] = nv3;                          \
    lv = __shfl_up_sync(0xffffffffu, v[3], 1);                               \
    if (lane == 0) lv = NEGV;                                                \
    if (((Y) & 7) == 7) {                                                    \
      if (lane >= 16)                                                        \
        s_dirs32[((Y) >> 3) * 128 + w * 16 + (lane - 16)] = bits_acc;        \
      bits_acc = 0u;                                                         \
    }                                                                        \
  }

#define MAS_EXCH8P()                                                         \
  {                                                                          \
    if (lane >= 16)                                                          \
      *(float4*)&s_exch[w * 64 + (lane - 16) * 4]                            \
          = make_float4(v[0], v[1], v[2], v[3]);                             \
    __syncthreads();                                                         \
    if (w > 0 && lane < 16) {                                                \
      float4 e = *(const float4*)&s_exch[(w - 1) * 64 + lane * 4];           \
      v[0] = e.x; v[1] = e.y; v[2] = e.z; v[3] = e.w;                        \
    }                                                                        \
    __syncthreads();                                                         \
    lv = __shfl_up_sync(0xffffffffu, v[3], 1);                               \
    if (lane == 0) lv = NEGV;                                                \
  }

#define LOADC_S(C, B)                                                        \
  {                                                                          \
    const float* s2 = nc + (size_t)(C) * 8 * TXn;                            \
    float* d2 = tiles + (B) * 4096;                                          \
    _Pragma("unroll") for (int i = 0; i < 4; i++)                            \
      cp16(d2 + (tid + i * 256) * 4, s2 + (tid + i * 256) * 4);              \
    CP_COMMIT();                                                             \
  }

#define SPIN_TILE(T)                                                         \
  {                                                                          \
    int _t = (T); if (_t > 15) _t = 15;                                      \
    int _need = tile_cnt(_t);                                                \
    volatile int* _fp = (volatile int*)&g_flags[b * 16 + _t];                \
    while (*_fp < _need) __nanosleep(64);                                    \
  }

// ---------------------------------------------------------------------------
// FUSED kernel: bid 0..15 = MAS consumers (persistent), bid 16.. = GEMM tiles
// in by-major / b-fastest order. GEMM signals g_flags[b][by] after tile store.
// ---------------------------------------------------------------------------
__global__ __launch_bounds__(256) void fused_kernel(
    const float* __restrict__ z,
    const float* __restrict__ logw,
    float* __restrict__ out_llen,
    float* __restrict__ out_attn) {
    extern __shared__ unsigned char s_dyn[];
    int tid = threadIdx.x;

    if (blockIdx.x >= 16) {
        // =================== GEMM producer path ===================
        int gid = blockIdx.x - 16;
        int by = 0, t = gid;
        for (int q = 0; q < 16; q++) {
            int lo = (q - 12 > 0) ? (q - 12) : 0;
            int hi = (q < 3) ? q : 3;
            int n = 16 * (hi - lo + 1);
            if (t < n) { by = q; break; }
            t -= n;
        }
        int bx0 = (by - 12 > 0) ? (by - 12) : 0;
        int bx  = bx0 + (t >> 4);
        int b   = t & 15;

        float* s_z  = (float*)s_dyn;            // [8][128]
        float* s_z2 = s_z  + 1024;
        float* s_ms = s_z2 + 1024;
        float* s_s  = s_ms + 1024;

        int lr = tid >> 5;
        int lc = (tid & 31) * 4;
        int ty = tid >> 4;
        int tx = tid & 15;
        int bsplit = ((lc >> 2) & 1) * 64 + (lc >> 3) * 4;

        const float* zb  = z     + b * Dn * TYn + by * 128;
        const float* msb = g_bms + b * Dn * TXn + bx * 128;
        const float* ssb = g_bs  + b * Dn * TXn + bx * 128;

        unsigned long long acc[8][4];
        #pragma unroll
        for (int i = 0; i < 8; i++)
            #pragma unroll
            for (int j = 0; j < 4; j++) acc[i][j] = 0ull;

        float4 az  = *(const float4*)(zb  + lr * TYn + lc);
        float4 ams = *(const float4*)(msb + lr * TXn + lc);
        float4 ass = *(const float4*)(ssb + lr * TXn + lc);

        for (int c = 0; c < Dn / 8; c++) {
            __syncthreads();
            {
                *(float4*)&s_z[lr * 128 + lc] = az;
                float4 az2 = make_float4(-0.5f * az.x * az.x, -0.5f * az.y * az.y,
                                         -0.5f * az.z * az.z, -0.5f * az.w * az.w);
                *(float4*)&s_z2[lr * 128 + lc] = az2;
                *(float4*)&s_ms[lr * 128 + bsplit] = ams;
                *(float4*)&s_s [lr * 128 + bsplit] = ass;
            }
            __syncthreads();

            if (c + 1 < Dn / 8) {
                int d0 = (c + 1) * 8;
                az  = *(const float4*)(zb  + (d0 + lr) * TYn + lc);
                ams = *(const float4*)(msb + (d0 + lr) * TXn + lc);
                ass = *(const float4*)(ssb + (d0 + lr) * TXn + lc);
            }

            #pragma unroll
            for (int kk = 0; kk < 8; kk++) {
                unsigned long long a1[8], a2[8], b1[4], b2[4];
                {
                    float4 t0 = *(const float4*)&s_z[kk * 128 + ty * 8];
                    float4 t1 = *(const float4*)&s_z[kk * 128 + ty * 8 + 4];
                    PACKDUP(a1[0], t0.x); PACKDUP(a1[1], t0.y);
                    PACKDUP(a1[2], t0.z); PACKDUP(a1[3], t0.w);
                    PACKDUP(a1[4], t1.x); PACKDUP(a1[5], t1.y);
                    PACKDUP(a1[6], t1.z); PACKDUP(a1[7], t1.w);
                }
                {
                    float4 t0 = *(const float4*)&s_z2[kk * 128 + ty * 8];
                    float4 t1 = *(const float4*)&s_z2[kk * 128 + ty * 8 + 4];
                    PACKDUP(a2[0], t0.x); PACKDUP(a2[1], t0.y);
                    PACKDUP(a2[2], t0.z); PACKDUP(a2[3], t0.w);
                    PACKDUP(a2[4], t1.x); PACKDUP(a2[5], t1.y);
                    PACKDUP(a2[6], t1.z); PACKDUP(a2[7], t1.w);
                }
                {
                    ulonglong2 lo = *(const ulonglong2*)&s_ms[kk * 128 + tx * 4];
                    ulonglong2 hi = *(const ulonglong2*)&s_ms[kk * 128 + 64 + tx * 4];
                    b1[0]=lo.x; b1[1]=lo.y; b1[2]=hi.x; b1[3]=hi.y;
                }
                {
                    ulonglong2 lo = *(const ulonglong2*)&s_s[kk * 128 + tx * 4];
                    ulonglong2 hi = *(const ulonglong2*)&s_s[kk * 128 + 64 + tx * 4];
                    b2[0]=lo.x; b2[1]=lo.y; b2[2]=hi.x; b2[3]=hi.y;
                }
                #pragma unroll
                for (int i = 0; i < 8; i++)
                    #pragma unroll
                    for (int j = 0; j < 4; j++) {
                        fma2(acc[i][j], a1[i], b1[j]);
                        fma2(acc[i][j], a2[i], b2[j]);
                    }
            }
        }

        float cv[8];
        *(float4*)&cv[0] = *(const float4*)(g_cvec + b * TXn + bx * 128 + tx * 8);
        *(float4*)&cv[4] = *(const float4*)(g_cvec + b * TXn + bx * 128 + tx * 8 + 4);

        float* outp = g_nc + (size_t)b * TYn * TXn + (size_t)(by * 128 + ty * 8) * TXn
                    + bx * 128 + tx * 8;
        #pragma unroll
        for (int i = 0; i < 8; i++) {
            float2 f0 = *(float2*)&acc[i][0];
            float2 f1 = *(float2*)&acc[i][1];
            float2 f2 = *(float2*)&acc[i][2];
            float2 f3 = *(float2*)&acc[i][3];
            float4 o0 = make_float4(f0.x + cv[0], f0.y + cv[1], f1.x + cv[2], f1.y + cv[3]);
            float4 o1 = make_float4(f2.x + cv[4], f2.y + cv[5], f3.x + cv[6], f3.y + cv[7]);
            *(float4*)(outp + (size_t)i * TXn)     = o0;
            *(float4*)(outp + (size_t)i * TXn + 4) = o1;
        }

        __threadfence();
        __syncthreads();
        if (tid == 0) atomicAdd(&g_flags[b * 16 + by], 1);
        return;
    }

    // =================== MAS consumer path ===================
    unsigned int* s_dirs32 = (unsigned int*)s_dyn;       // 128 KB
    float* tiles = (float*)(s_dyn + TYn * 64);           // 5 * 16KB = 80 KB
    __shared__ float s_exch[8 * 64];
    __shared__ unsigned short path_sm[TYn];
    __shared__ int w_sm[TXn];
    __shared__ float s_red[8];

    int b = blockIdx.x;
    int w = tid >> 5, lane = tid & 31;
    const float* nc = g_nc + (size_t)b * TYn * TXn;
    int c0 = (w - 1) * 64 + lane * 4;            // negative in warp-0 halo
    int ldoff = (c0 < 0) ? (lane * 4) : c0;

    if (tid == 0) SPIN_TILE(0);
    __syncthreads();

    float v[4];
    #pragma unroll
    for (int i = 0; i < 4; i++) v[i] = NEGV;
    if (c0 == 0) v[0] = nc[0];
    unsigned int bits_acc = 0u;

    const int NCH = TYn / 8;                     // 256

    LOADC_S(0, 0);
    LOADC_S(1, 1);
    LOADC_S(2, 2);
    LOADC_S(3, 3);
    CP_WAIT3();                                  // chunk 0 complete
    __syncthreads();

    float lv = __shfl_up_sync(0xffffffffu, v[3], 1);
    if (lane == 0) lv = NEGV;
    float4 pf = *(const float4*)(tiles + 512 + ldoff);   // buf0 row 1

    // chunk 0: rows 1..7
    {
        float* bp = tiles;
        ROWP(1, bp + 2 * 512 + ldoff, 1);
        ROWP(2, bp + 3 * 512 + ldoff, 1);
        ROWP(3, bp + 4 * 512 + ldoff, 1);
        ROWP(4, bp + 5 * 512 + ldoff, 1);
        ROWP(5, bp + 6 * 512 + ldoff, 1);
        ROWP(6, bp + 7 * 512 + ldoff, 1);
        CP_WAIT2();                              // chunk 1 complete
        __syncthreads();
        LOADC_S(4, 4);
        ROWP(7, tiles + 1 * 4096 + ldoff, 1);    // pf <- buf1 row 0
    }

    for (int c = 1; c < NCH; c++) {
        float* bp = tiles + (c % 5) * 4096;
        int yb = c * 8;
        int M = (c < 64);
        if (M) {
            ROWP(yb + 0, bp + 1 * 512 + ldoff, 1);
            ROWP(yb + 1, bp + 2 * 512 + ldoff, 1);
            ROWP(yb + 2, bp + 3 * 512 + ldoff, 1);
            ROWP(yb + 3, bp + 4 * 512 + ldoff, 1);
            ROWP(yb + 4, bp + 5 * 512 + ldoff, 1);
            ROWP(yb + 5, bp + 6 * 512 + ldoff, 1);
            ROWP(yb + 6, bp + 7 * 512 + ldoff, 1);
        } else {
            ROWP(yb + 0, bp + 1 * 512 + ldoff, 0);
            ROWP(yb + 1, bp + 2 * 512 + ldoff, 0);
            ROWP(yb + 2, bp + 3 * 512 + ldoff, 0);
            ROWP(yb + 3, bp + 4 * 512 + ldoff, 0);
            ROWP(yb + 4, bp + 5 * 512 + ldoff, 0);
            ROWP(yb + 5, bp + 6 * 512 + ldoff, 0);
            ROWP(yb + 6, bp + 7 * 512 + ldoff, 0);
        }
        // ensure chunk c+1 complete (last committed so far = c+3)
        int rem = NCH - 2 - c;
        if (rem >= 2)      { CP_WAIT2(); }
        else if (rem == 1) { CP_WAIT1(); }
        else               { CP_WAIT0(); }
        if (c + 4 < NCH) { if (tid == 0) SPIN_TILE((c + 4) >> 4); }
        __syncthreads();
        if (c + 4 < NCH) LOADC_S(c + 4, (c + 4) % 5);
        float* np = (c + 1 < NCH) ? (tiles + ((c + 1) % 5) * 4096 + ldoff)
                                  : (bp + 7 * 512 + ldoff);
        if (M) { ROWP(yb + 7, np, 1); } else { ROWP(yb + 7, np, 0); }
        if ((c & 7) == 7 && c + 1 < NCH) MAS_EXCH8P();
    }
    __syncthreads();

    // pipelined backtrack: 8-row blocks, 3 candidate words per block
    if (tid == 0) {
        int idx = TXn - 1;
        for (int k = (TYn / 8) - 1; k >= 0; k--) {
            int g = idx >> 2;
            unsigned int w0 = s_dirs32[k * 128 + g];
            unsigned int w1 = (g >= 1) ? s_dirs32[k * 128 + g - 1] : 0u;
            unsigned int w2 = (g >= 2) ? s_dirs32[k * 128 + g - 2] : 0u;
            #pragma unroll
            for (int r = 7; r >= 0; r--) {
                int yy = k * 8 + r;
                if (yy == 0) break;
                path_sm[yy] = (unsigned short)idx;
                int gg = idx >> 2;
                unsigned int word = (gg == g) ? w0 : ((gg == g - 1) ? w1 : w2);
                int bitpos = ((yy & 7) << 2) + (idx & 3);
                idx -= (int)((word >> bitpos) & 1u);
            }
        }
        path_sm[0] = (unsigned short)idx;
    }
    __syncthreads();

    for (int x = tid; x < TXn; x += 256) w_sm[x] = 0;
    __syncthreads();

    for (int yy = tid; yy < TYn; yy += 256) {
        int px = path_sm[yy];
        g_path[b * TYn + yy] = px;
        atomicAdd(&w_sm[px], 1);
        out_attn[(size_t)b * TYn * TXn + (size_t)yy * TXn + px] = 1.0f;
    }
    __syncthreads();

    float part = 0.0f;
    for (int x = tid; x < TXn; x += 256) {
        float lw = logw[b * TXn + x];
        float d  = lw - logf((float)w_sm[x] + 1e-6f);
        part += d * d;
    }
    #pragma unroll
    for (int o = 16; o > 0; o >>= 1)
        part += __shfl_down_sync(0xffffffffu, part, o);
    if (lane == 0) s_red[w] = part;
    __syncthreads();
    if (tid == 0) {
        float s = 0.0f;
        #pragma unroll
        for (int i = 0; i < 8; i++) s += s_red[i];
        out_llen[b] = s;
    }
}

// ---------------------------------------------------------------------------
// Kernel 4: gather
// ---------------------------------------------------------------------------
__global__ void gather_kernel(const float* __restrict__ xm,
                              const float* __restrict__ xl,
                              float* __restrict__ out_main) {
    int b  = blockIdx.y;
    int dc = blockIdx.z;
    int y  = blockIdx.x * 256 + threadIdx.x;
    int px = g_path[b * TYn + y];
    const float* xmb = xm + b * Dn * TXn + px;
    const float* xlb = xl + b * Dn * TXn + px;
    float* o = out_main + (size_t)b * 2 * Dn * TYn + y;
    int d0 = dc * 24;
    #pragma unroll 4
    for (int d = d0; d < d0 + 24; d++)
        o[(size_t)d * TYn] = xmb[(size_t)d * TXn];
    #pragma unroll 4
    for (int d = d0; d < d0 + 24; d++)
        o[(size_t)(Dn + d) * TYn] = xlb[(size_t)d * TXn];
}

// ---------------------------------------------------------------------------
extern "C" void kernel_launch(void* const* d_in, const int* in_sizes, int n_in,
                              void* d_out, int out_size) {
    const float* xm   = (const float*)d_in[0];
    const float* xl   = (const float*)d_in[1];
    const float* z    = (const float*)d_in[2];
    const float* logw = (const float*)d_in[3];

    float* out       = (float*)d_out;
    const size_t OM  = (size_t)Bn * 2 * Dn * TYn;
    float* out_main  = out;
    float* out_llen  = out + OM;
    float* out_attn  = out + OM + Bn;

    int fused_smem = TYn * 64 + 5 * 4096 * (int)sizeof(float);  // 128K + 80K
    cudaFuncSetAttribute(fused_kernel,
                         cudaFuncAttributeMaxDynamicSharedMemorySize, fused_smem);

    // kernels: dummy(1) prep(2) combine(3) fused(4 - captured) gather(5)
    dummy_kernel<<<1, 1>>>();
    prep_kernel<<<dim3(TXn / 128, Bn, 8), 128>>>(xm, xl);
    combine_kernel<<<(Bn * TXn) / 256, 256>>>();
    cudaMemsetAsync(out_attn, 0, (size_t)Bn * TYn * TXn * sizeof(float));
    fused_kernel<<<16 + 832, 256, fused_smem>>>(z, logw, out_llen, out_attn);
    gather_kernel<<<dim3(TYn / 256, Bn, 8), 256>>>(xm, xl, out_main);
}